// round 5
// baseline (speedup 1.0000x reference)
#include <cuda_runtime.h>
#include <math.h>
#include <limits.h>

// Problem constants: B=4096, DIM=512, C=128, TEMP=0.05
#define MAXB 8192
#define MAXC 128
#define DIM  512
#define CHUNK 32
#define PAD   513   // 513 mod 32 == 1 -> lane l, col k hits bank (l+k)%32: conflict-free

__device__ int   g_lab[MAXB];
__device__ int   g_bstart[MAXC + 1];
__device__ int   g_bidx[MAXB];
__device__ float g_sum;
__device__ float g_cnt;
__device__ int   g_done;

// ---------------------------------------------------------------------------
// Kernel 1: build label buckets (CSR) + zero accumulators. Single block.
// ---------------------------------------------------------------------------
__global__ void __launch_bounds__(1024)
build_kernel(const int* __restrict__ labels, int n, int C)
{
    __shared__ int s_cnt[MAXC];
    __shared__ int s_scat[MAXC];
    __shared__ int s_wsum[4];
    __shared__ int s_lab[MAXB];
    int tid = threadIdx.x;

    for (int c = tid; c < MAXC; c += blockDim.x) s_cnt[c] = 0;
    if (tid == 0) { g_sum = 0.0f; g_cnt = 0.0f; g_done = 0; }
    __syncthreads();

    for (int i = tid; i < n; i += blockDim.x) {
        int l = labels[i];
        l = (l < 0) ? 0 : (l >= C ? C - 1 : l);
        s_lab[i] = l;
        g_lab[i] = l;
        atomicAdd(&s_cnt[l], 1);
    }
    __syncthreads();

    int incl_local = 0;
    if (tid < MAXC) {
        int lane = tid & 31, w = tid >> 5;
        int x = s_cnt[tid];
        #pragma unroll
        for (int o = 1; o < 32; o <<= 1) {
            int y = __shfl_up_sync(0xFFFFFFFFu, x, o);
            if (lane >= o) x += y;
        }
        if (lane == 31) s_wsum[w] = x;
        incl_local = x;
    }
    __syncthreads();
    if (tid < MAXC) {
        int w = tid >> 5;
        int add = 0;
        #pragma unroll
        for (int k = 0; k < 4; k++) add += (k < w) ? s_wsum[k] : 0;
        int incl = incl_local + add;
        int excl = incl - s_cnt[tid];
        g_bstart[tid] = excl;
        s_scat[tid]   = excl;
        if (tid == MAXC - 1) g_bstart[MAXC] = incl;
    }
    __syncthreads();

    for (int i = tid; i < n; i += blockDim.x) {
        int l = s_lab[i];
        int p = atomicAdd(&s_scat[l], 1);
        g_bidx[p] = i;
    }
}

// ---------------------------------------------------------------------------
__device__ __forceinline__ float warp_sum(float v)
{
    #pragma unroll
    for (int o = 16; o > 0; o >>= 1)
        v += __shfl_xor_sync(0xFFFFFFFFu, v, o);
    return v;
}

// direct squared distance between global rows a,b (warp-cooperative)
__device__ __forceinline__ float direct_d2(const float* __restrict__ batch,
                                           int a, int b, int lane)
{
    const float4* ra = (const float4*)(batch + (size_t)a * DIM);
    const float4* rb = (const float4*)(batch + (size_t)b * DIM);
    float c0 = 0.f, c1 = 0.f;
    #pragma unroll
    for (int q = 0; q < 4; q++) {
        float4 x = ra[lane + 32 * q];
        float4 y = rb[lane + 32 * q];
        float d;
        d = x.x - y.x; c0 = fmaf(d, d, c0);
        d = x.y - y.y; c1 = fmaf(d, d, c1);
        d = x.z - y.z; c0 = fmaf(d, d, c0);
        d = x.w - y.w; c1 = fmaf(d, d, c1);
    }
    return warp_sum(c0 + c1);
}

extern __shared__ float s_j[];   // CHUNK rows x PAD floats (dynamic, 65664 B)

// ---------------------------------------------------------------------------
// Kernel 2: one block per label bucket.
// ---------------------------------------------------------------------------
__global__ void __launch_bounds__(256)
bucket_kernel(const float* __restrict__ batch,
              const int* __restrict__ anchors,
              const int* __restrict__ negatives,
              float* __restrict__ out)
{
    __shared__ float s_n[CHUNK];
    __shared__ int   s_ji[CHUNK];
    __shared__ float s_bsum;
    __shared__ int   s_bcnt;

    int c    = blockIdx.x;
    int s    = g_bstart[c];
    int e    = g_bstart[c + 1];
    int cnt  = e - s;
    int tid  = threadIdx.x;
    int w    = tid >> 5;
    int lane = tid & 31;

    if (tid == 0) { s_bsum = 0.f; s_bcnt = 0; }

    if (cnt > 2) {
        // groups of up to 64 anchor slots (8 warps x 8 slot regs)
        for (int sbase = s; sbase < e; sbase += 64) {
            float best[8]; int bj[8];
            #pragma unroll
            for (int g = 0; g < 8; g++) { best[g] = INFINITY; bj[g] = INT_MAX; }

            for (int base = s; base < e; base += CHUNK) {
                int cm = min(CHUNK, e - base);
                __syncthreads();   // previous chunk consumers done
                // stage cm candidate rows into padded smem
                for (int idx = tid; idx < cm * 128; idx += 256) {
                    int r  = idx >> 7;
                    int k4 = idx & 127;
                    int j  = g_bidx[base + r];
                    float4 v = ((const float4*)(batch + (size_t)j * DIM))[k4];
                    float* dst = s_j + r * PAD + k4 * 4;
                    dst[0] = v.x; dst[1] = v.y; dst[2] = v.z; dst[3] = v.w;
                }
                if (tid < cm) s_ji[tid] = g_bidx[base + tid];
                __syncthreads();
                // norms of chunk rows
                for (int r = w; r < cm; r += 8) {
                    const float* rp = s_j + r * PAD;
                    float a0 = 0.f;
                    #pragma unroll
                    for (int q = 0; q < 16; q++) {
                        float x = rp[lane + 32 * q];
                        a0 = fmaf(x, x, a0);
                    }
                    a0 = warp_sum(a0);
                    if (lane == 0) s_n[r] = a0;
                }
                __syncthreads();

                int   jn = (lane < cm) ? s_ji[lane] : -1;
                float nj = (lane < cm) ? s_n[lane]  : 0.f;
                const float* sl = s_j + lane * PAD;

                #pragma unroll
                for (int q = 0; q < 2; q++) {
                    int sl0 = sbase + w + 8 * (4 * q + 0);
                    int sl1 = sbase + w + 8 * (4 * q + 1);
                    int sl2 = sbase + w + 8 * (4 * q + 2);
                    int sl3 = sbase + w + 8 * (4 * q + 3);
                    bool v0 = sl0 < e, v1 = sl1 < e, v2 = sl2 < e, v3 = sl3 < e;
                    int t0 = g_bidx[v0 ? sl0 : s];
                    int t1 = g_bidx[v1 ? sl1 : s];
                    int t2 = g_bidx[v2 ? sl2 : s];
                    int t3 = g_bidx[v3 ? sl3 : s];
                    const float4* p0 = (const float4*)(batch + (size_t)t0 * DIM);
                    const float4* p1 = (const float4*)(batch + (size_t)t1 * DIM);
                    const float4* p2 = (const float4*)(batch + (size_t)t2 * DIM);
                    const float4* p3 = (const float4*)(batch + (size_t)t3 * DIM);

                    float a0 = 0.f, b0 = 0.f, a1 = 0.f, b1 = 0.f;
                    float a2 = 0.f, b2 = 0.f, a3 = 0.f, b3 = 0.f;
                    #pragma unroll 4
                    for (int k4 = 0; k4 < 128; k4++) {
                        float s0 = sl[k4 * 4 + 0];
                        float s1 = sl[k4 * 4 + 1];
                        float s2 = sl[k4 * 4 + 2];
                        float s3 = sl[k4 * 4 + 3];
                        float4 A = p0[k4];
                        a0 = fmaf(A.x, s0, a0); b0 = fmaf(A.y, s1, b0);
                        a0 = fmaf(A.z, s2, a0); b0 = fmaf(A.w, s3, b0);
                        float4 B = p1[k4];
                        a1 = fmaf(B.x, s0, a1); b1 = fmaf(B.y, s1, b1);
                        a1 = fmaf(B.z, s2, a1); b1 = fmaf(B.w, s3, b1);
                        float4 Cv = p2[k4];
                        a2 = fmaf(Cv.x, s0, a2); b2 = fmaf(Cv.y, s1, b2);
                        a2 = fmaf(Cv.z, s2, a2); b2 = fmaf(Cv.w, s3, b2);
                        float4 Dv = p3[k4];
                        a3 = fmaf(Dv.x, s0, a3); b3 = fmaf(Dv.y, s1, b3);
                        a3 = fmaf(Dv.z, s2, a3); b3 = fmaf(Dv.w, s3, b3);
                    }
                    if (jn >= 0) {
                        float m;
                        m = nj - 2.f * (a0 + b0);
                        if (v0 && jn != t0 &&
                            (m < best[4*q+0] || (m == best[4*q+0] && jn < bj[4*q+0])))
                            { best[4*q+0] = m; bj[4*q+0] = jn; }
                        m = nj - 2.f * (a1 + b1);
                        if (v1 && jn != t1 &&
                            (m < best[4*q+1] || (m == best[4*q+1] && jn < bj[4*q+1])))
                            { best[4*q+1] = m; bj[4*q+1] = jn; }
                        m = nj - 2.f * (a2 + b2);
                        if (v2 && jn != t2 &&
                            (m < best[4*q+2] || (m == best[4*q+2] && jn < bj[4*q+2])))
                            { best[4*q+2] = m; bj[4*q+2] = jn; }
                        m = nj - 2.f * (a3 + b3);
                        if (v3 && jn != t3 &&
                            (m < best[4*q+3] || (m == best[4*q+3] && jn < bj[4*q+3])))
                            { best[4*q+3] = m; bj[4*q+3] = jn; }
                    }
                }
            } // chunks

            // finalize this group's slots
            #pragma unroll
            for (int g = 0; g < 8; g++) {
                int slot = sbase + w + 8 * g;
                if (slot < e) {   // uniform across the warp (depends on w only)
                    float b = best[g]; int j = bj[g];
                    #pragma unroll
                    for (int o = 16; o > 0; o >>= 1) {
                        float ob = __shfl_xor_sync(0xFFFFFFFFu, b, o);
                        int   oj = __shfl_xor_sync(0xFFFFFFFFu, j, o);
                        if (ob < b || (ob == b && oj < j)) { b = ob; j = oj; }
                    }
                    int t  = g_bidx[slot];
                    int a  = anchors[t];
                    int ng = negatives[t];
                    float dap2 = direct_d2(batch, a, j,  lane);
                    float dan2 = direct_d2(batch, a, ng, lane);
                    if (lane == 0) {
                        float d_ap = sqrtf(fmaxf(dap2, 1e-12f));
                        float d_an = sqrtf(fmaxf(dan2, 1e-12f));
                        float z    = (d_ap - d_an) * 10.0f;   // (s_an - s_ap)/0.05
                        float per  = fmaxf(z, 0.f) + log1pf(expf(-fabsf(z)));
                        atomicAdd(&s_bsum, per);
                        atomicAdd(&s_bcnt, 1);
                    }
                }
            }
        } // groups
    }

    __syncthreads();
    if (tid == 0) {
        if (s_bcnt > 0) {
            atomicAdd(&g_sum, s_bsum);
            atomicAdd(&g_cnt, (float)s_bcnt);
        }
        __threadfence();
        int done = atomicAdd(&g_done, 1);
        if (done == (int)gridDim.x - 1) {
            float sum = atomicAdd(&g_sum, 0.0f);
            float cn  = atomicAdd(&g_cnt, 0.0f);
            out[0] = sum / cn;
        }
    }
}

// ---------------------------------------------------------------------------
extern "C" void kernel_launch(void* const* d_in, const int* in_sizes, int n_in,
                              void* d_out, int out_size)
{
    const float* batch     = (const float*)d_in[0];
    const int*   labels    = (const int*)d_in[1];
    const int*   anchors   = (const int*)d_in[2];
    const int*   negatives = (const int*)d_in[3];
    float*       out       = (float*)d_out;

    int n = in_sizes[1];
    int C = 128;
    int dyn = CHUNK * PAD * (int)sizeof(float);   // 65664 B

    cudaFuncSetAttribute(bucket_kernel,
                         cudaFuncAttributeMaxDynamicSharedMemorySize, dyn);

    build_kernel<<<1, 1024>>>(labels, n, C);
    bucket_kernel<<<C, 256, dyn>>>(batch, anchors, negatives, out);
}

// round 6
// speedup vs baseline: 2.9416x; 2.9416x over previous
#include <cuda_runtime.h>
#include <math.h>
#include <limits.h>

// Problem constants: B=4096, DIM=512, C=128, TEMP=0.05
#define MAXB 8192
#define MAXC 128
#define DIM  512

__device__ int   g_lab[MAXB];
__device__ int   g_bstart[MAXC + 1];
__device__ int   g_bidx[MAXB];
__device__ float g_sum;
__device__ float g_cnt;
__device__ int   g_done;

// ---------------------------------------------------------------------------
// Kernel 1: build label buckets (CSR) + zero accumulators. Single block.
// ---------------------------------------------------------------------------
__global__ void __launch_bounds__(1024)
build_kernel(const int* __restrict__ labels, int n, int C)
{
    __shared__ int s_cnt[MAXC];
    __shared__ int s_scat[MAXC];
    __shared__ int s_wsum[4];
    __shared__ int s_lab[MAXB];
    int tid = threadIdx.x;

    for (int c = tid; c < MAXC; c += blockDim.x) s_cnt[c] = 0;
    if (tid == 0) { g_sum = 0.0f; g_cnt = 0.0f; g_done = 0; }
    __syncthreads();

    for (int i = tid; i < n; i += blockDim.x) {
        int l = labels[i];
        l = (l < 0) ? 0 : (l >= C ? C - 1 : l);
        s_lab[i] = l;
        g_lab[i] = l;
        atomicAdd(&s_cnt[l], 1);
    }
    __syncthreads();

    int incl_local = 0;
    if (tid < MAXC) {
        int lane = tid & 31, w = tid >> 5;
        int x = s_cnt[tid];
        #pragma unroll
        for (int o = 1; o < 32; o <<= 1) {
            int y = __shfl_up_sync(0xFFFFFFFFu, x, o);
            if (lane >= o) x += y;
        }
        if (lane == 31) s_wsum[w] = x;
        incl_local = x;
    }
    __syncthreads();
    if (tid < MAXC) {
        int w = tid >> 5;
        int add = 0;
        #pragma unroll
        for (int k = 0; k < 4; k++) add += (k < w) ? s_wsum[k] : 0;
        int incl = incl_local + add;
        int excl = incl - s_cnt[tid];
        g_bstart[tid] = excl;
        s_scat[tid]   = excl;
        if (tid == MAXC - 1) g_bstart[MAXC] = incl;
    }
    __syncthreads();

    for (int i = tid; i < n; i += blockDim.x) {
        int l = s_lab[i];
        int p = atomicAdd(&s_scat[l], 1);
        g_bidx[p] = i;
    }
}

// ---------------------------------------------------------------------------
__device__ __forceinline__ float warp_sum(float v)
{
    #pragma unroll
    for (int o = 16; o > 0; o >>= 1)
        v += __shfl_xor_sync(0xFFFFFFFFu, v, o);
    return v;
}

// ---------------------------------------------------------------------------
// Kernel 2: one warp per triplet (bucket order), 4 candidates per iteration.
// ---------------------------------------------------------------------------
__global__ void __launch_bounds__(256)
triplet_kernel(const float* __restrict__ batch,
               const int* __restrict__ anchors,
               const int* __restrict__ negatives,
               int n, float* __restrict__ out)
{
    int gw   = (blockIdx.x * blockDim.x + threadIdx.x) >> 5;
    int lane = threadIdx.x & 31;

    if (gw < n) {
        int t   = g_bidx[gw];          // anchor row (bucket order for L1 locality)
        int lab = g_lab[t];
        int s   = g_bstart[lab];
        int e   = g_bstart[lab + 1];
        int cnt = e - s;

        // anchor row in registers: 4 float4 per lane
        const float4* rt = (const float4*)(batch + (size_t)t * DIM);
        float4 xi0 = rt[lane];
        float4 xi1 = rt[lane + 32];
        float4 xi2 = rt[lane + 64];
        float4 xi3 = rt[lane + 96];

        float best  = INFINITY;
        int   bestj = INT_MAX;

        for (int p = s; p < e; p += 4) {
            int p1 = p + 1, p2 = p + 2, p3 = p + 3;
            bool v1 = p1 < e, v2 = p2 < e, v3 = p3 < e;
            int j0 = g_bidx[p];
            int j1 = g_bidx[v1 ? p1 : p];
            int j2 = g_bidx[v2 ? p2 : p];
            int j3 = g_bidx[v3 ? p3 : p];
            const float4* r0 = (const float4*)(batch + (size_t)j0 * DIM);
            const float4* r1 = (const float4*)(batch + (size_t)j1 * DIM);
            const float4* r2 = (const float4*)(batch + (size_t)j2 * DIM);
            const float4* r3 = (const float4*)(batch + (size_t)j3 * DIM);

            // 4 candidates, each with 2 independent FMA chains
            float a0 = 0.f, b0 = 0.f, a1 = 0.f, b1 = 0.f;
            float a2 = 0.f, b2 = 0.f, a3 = 0.f, b3 = 0.f;
            #pragma unroll
            for (int q = 0; q < 4; q++) {
                float4 x = (q == 0) ? xi0 : (q == 1) ? xi1 : (q == 2) ? xi2 : xi3;
                float4 y0 = r0[lane + 32 * q];
                float4 y1 = r1[lane + 32 * q];
                float4 y2 = r2[lane + 32 * q];
                float4 y3 = r3[lane + 32 * q];
                float d;
                d = x.x - y0.x; a0 = fmaf(d, d, a0);
                d = x.x - y1.x; a1 = fmaf(d, d, a1);
                d = x.x - y2.x; a2 = fmaf(d, d, a2);
                d = x.x - y3.x; a3 = fmaf(d, d, a3);
                d = x.y - y0.y; b0 = fmaf(d, d, b0);
                d = x.y - y1.y; b1 = fmaf(d, d, b1);
                d = x.y - y2.y; b2 = fmaf(d, d, b2);
                d = x.y - y3.y; b3 = fmaf(d, d, b3);
                d = x.z - y0.z; a0 = fmaf(d, d, a0);
                d = x.z - y1.z; a1 = fmaf(d, d, a1);
                d = x.z - y2.z; a2 = fmaf(d, d, a2);
                d = x.z - y3.z; a3 = fmaf(d, d, a3);
                d = x.w - y0.w; b0 = fmaf(d, d, b0);
                d = x.w - y1.w; b1 = fmaf(d, d, b1);
                d = x.w - y2.w; b2 = fmaf(d, d, b2);
                d = x.w - y3.w; b3 = fmaf(d, d, b3);
            }
            float s0 = a0 + b0, s1 = a1 + b1, s2 = a2 + b2, s3 = a3 + b3;

            // 4 interleaved butterflies (independent -> pipelined)
            #pragma unroll
            for (int o = 16; o > 0; o >>= 1) {
                s0 += __shfl_xor_sync(0xFFFFFFFFu, s0, o);
                s1 += __shfl_xor_sync(0xFFFFFFFFu, s1, o);
                s2 += __shfl_xor_sync(0xFFFFFFFFu, s2, o);
                s3 += __shfl_xor_sync(0xFFFFFFFFu, s3, o);
            }

            if (j0 != t && (s0 < best || (s0 == best && j0 < bestj))) { best = s0; bestj = j0; }
            if (v1 && j1 != t && (s1 < best || (s1 == best && j1 < bestj))) { best = s1; bestj = j1; }
            if (v2 && j2 != t && (s2 < best || (s2 == best && j2 < bestj))) { best = s2; bestj = j2; }
            if (v3 && j3 != t && (s3 < best || (s3 == best && j3 < bestj))) { best = s3; bestj = j3; }
        }

        if (cnt > 2) {                 // valid: sum(posmask) > 1
            int a  = anchors[t];
            int ng = negatives[t];

            // d_ap^2 : a == t in this dataset -> reuse best; else recompute
            float dap2;
            if (a == t) {
                dap2 = best;
            } else {
                const float4* ra = (const float4*)(batch + (size_t)a * DIM);
                const float4* rp = (const float4*)(batch + (size_t)bestj * DIM);
                float ca = 0.f, cb = 0.f;
                #pragma unroll
                for (int q = 0; q < 4; q++) {
                    float4 x = ra[lane + 32 * q];
                    float4 y = rp[lane + 32 * q];
                    float d;
                    d = x.x - y.x; ca = fmaf(d, d, ca);
                    d = x.y - y.y; cb = fmaf(d, d, cb);
                    d = x.z - y.z; ca = fmaf(d, d, ca);
                    d = x.w - y.w; cb = fmaf(d, d, cb);
                }
                dap2 = warp_sum(ca + cb);
            }

            // d_an^2
            float dan2;
            {
                const float4* rn = (const float4*)(batch + (size_t)ng * DIM);
                float ca = 0.f, cb = 0.f;
                if (a == t) {
                    float4 xs[4] = {xi0, xi1, xi2, xi3};
                    #pragma unroll
                    for (int q = 0; q < 4; q++) {
                        float4 y = rn[lane + 32 * q];
                        float d;
                        d = xs[q].x - y.x; ca = fmaf(d, d, ca);
                        d = xs[q].y - y.y; cb = fmaf(d, d, cb);
                        d = xs[q].z - y.z; ca = fmaf(d, d, ca);
                        d = xs[q].w - y.w; cb = fmaf(d, d, cb);
                    }
                } else {
                    const float4* ra = (const float4*)(batch + (size_t)a * DIM);
                    #pragma unroll
                    for (int q = 0; q < 4; q++) {
                        float4 x = ra[lane + 32 * q];
                        float4 y = rn[lane + 32 * q];
                        float d;
                        d = x.x - y.x; ca = fmaf(d, d, ca);
                        d = x.y - y.y; cb = fmaf(d, d, cb);
                        d = x.z - y.z; ca = fmaf(d, d, ca);
                        d = x.w - y.w; cb = fmaf(d, d, cb);
                    }
                }
                dan2 = warp_sum(ca + cb);
            }

            if (lane == 0) {
                float d_ap = sqrtf(fmaxf(dap2, 1e-12f));
                float d_an = sqrtf(fmaxf(dan2, 1e-12f));
                float z    = (d_ap - d_an) * 10.0f;   // (s_an - s_ap)/0.05
                float per  = fmaxf(z, 0.f) + log1pf(expf(-fabsf(z)));
                atomicAdd(&g_sum, per);
                atomicAdd(&g_cnt, 1.0f);
            }
        }
    }

    // fused finalize: last block writes output
    __syncthreads();
    if (threadIdx.x == 0) {
        __threadfence();
        int done = atomicAdd(&g_done, 1);
        if (done == (int)gridDim.x - 1) {
            float sum = atomicAdd(&g_sum, 0.0f);
            float cn  = atomicAdd(&g_cnt, 0.0f);
            out[0] = sum / cn;
        }
    }
}

// ---------------------------------------------------------------------------
extern "C" void kernel_launch(void* const* d_in, const int* in_sizes, int n_in,
                              void* d_out, int out_size)
{
    const float* batch     = (const float*)d_in[0];
    const int*   labels    = (const int*)d_in[1];
    const int*   anchors   = (const int*)d_in[2];
    const int*   negatives = (const int*)d_in[3];
    float*       out       = (float*)d_out;

    int n = in_sizes[1];
    int C = 128;

    build_kernel<<<1, 1024>>>(labels, n, C);

    int warps_per_block = 256 / 32;
    int grid = (n + warps_per_block - 1) / warps_per_block;
    triplet_kernel<<<grid, 256>>>(batch, anchors, negatives, n, out);
}